// round 9
// baseline (speedup 1.0000x reference)
#include <cuda_runtime.h>
#include <cstddef>

// ---------------------------------------------------------------------------
// CausalSelfAttention: y = proj( softmax_causal( (xWa+ba)_q (xWa+ba)_k^T / sqrt(hd) ) (xWa+ba)_v )
// B=4, T=2048, C=1024, NH=16, HD=64. Full fp32 via packed fma.rn.f32x2 (FFMA2).
// Stage 1: QKV GEMM  [8192,1024]x[1024,3072] -> g_qkv
// Stage 2: flash attention (64x64 tiles, online softmax) -> g_y  [B,T,C] layout
// Stage 3: proj GEMM [8192,1024]x[1024,1024] -> d_out
// ---------------------------------------------------------------------------

typedef unsigned long long ull;

#define B_  4
#define T_  2048
#define C_  1024
#define NH_ 16
#define HD_ 64
#define M_  (B_ * T_)   // 8192
#define N3C (3 * C_)    // 3072

// scratch (static device globals: allocation-guard safe)
__device__ float g_qkv[(size_t)M_ * N3C];  // [8192][3072]
__device__ float g_y[(size_t)M_ * C_];     // [8192][1024]

union F4U {
    float4 f;
    float  a[4];
    ull    p[2];
};

__device__ __forceinline__ ull pack2(float x, float y) {
    ull r;
    asm("mov.b64 %0, {%1, %2};" : "=l"(r) : "f"(x), "f"(y));
    return r;
}
__device__ __forceinline__ float2 unpack2(ull v) {
    float2 r;
    asm("mov.b64 {%0, %1}, %2;" : "=f"(r.x), "=f"(r.y) : "l"(v));
    return r;
}
// d = a * b + d  (packed 2 x fp32, Blackwell FFMA2)
__device__ __forceinline__ void fma2(ull& d, ull a, ull b) {
    asm("fma.rn.f32x2 %0, %1, %2, %0;" : "+l"(d) : "l"(a), "l"(b));
}
__device__ __forceinline__ ull mul2(ull a, ull b) {
    ull d;
    asm("mul.rn.f32x2 %0, %1, %2;" : "=l"(d) : "l"(a), "l"(b));
    return d;
}

// ---------------------------------------------------------------------------
// SGEMM: C[m][n] = sum_k A[m][k] * W[k][n] + bias[n]
// 128x128 block tile, BK=8, 256 threads, 8x8 micro-tile (8 rows x 4 f32x2 cols)
// ---------------------------------------------------------------------------
#define GBM 128
#define GBN 128
#define GBK 8

__device__ __forceinline__ void gemm_tile(
    const float* __restrict__ A, const float* __restrict__ W,
    const float* __restrict__ bias, float* __restrict__ Cc,
    int N, int K)
{
    __shared__ float As[GBK][GBM];   // A staged transposed: As[k][m]
    __shared__ float Bs[GBK][GBN];

    const int tid = threadIdx.x;     // 256
    const int tx  = tid & 15;
    const int ty  = tid >> 4;
    const int m0  = blockIdx.y * GBM;
    const int n0  = blockIdx.x * GBN;

    const int arow = tid >> 1;         // 0..127
    const int acol = (tid & 1) << 2;   // 0 or 4
    const int brow = tid >> 5;         // 0..7
    const int bcol = (tid & 31) << 2;  // 0..124

    const float* Ap = A + (size_t)(m0 + arow) * K + acol;
    const float* Bp = W + (size_t)brow * N + n0 + bcol;

    ull acc[8][4];
#pragma unroll
    for (int i = 0; i < 8; ++i)
#pragma unroll
        for (int j = 0; j < 4; ++j) acc[i][j] = 0ull;

    for (int k0 = 0; k0 < K; k0 += GBK) {
        // gmem loads overlap previous tile's tail compute
        const float4 av = *(const float4*)(Ap + k0);
        const float4 bv = *(const float4*)(Bp + (size_t)k0 * N);
        __syncthreads();   // all readers of previous tile done
        As[acol + 0][arow] = av.x;
        As[acol + 1][arow] = av.y;
        As[acol + 2][arow] = av.z;
        As[acol + 3][arow] = av.w;
        *(float4*)&Bs[brow][bcol] = bv;
        __syncthreads();
#pragma unroll
        for (int k = 0; k < GBK; ++k) {
            F4U a0, a1, b0, b1;
            a0.f = *(const float4*)&As[k][ty * 8];
            a1.f = *(const float4*)&As[k][ty * 8 + 4];
            b0.f = *(const float4*)&Bs[k][tx * 8];
            b1.f = *(const float4*)&Bs[k][tx * 8 + 4];
            const ull bp0 = b0.p[0], bp1 = b0.p[1], bp2 = b1.p[0], bp3 = b1.p[1];
#pragma unroll
            for (int i = 0; i < 8; ++i) {
                const float aval = (i < 4) ? a0.a[i] : a1.a[i - 4];
                const ull ad = pack2(aval, aval);
                fma2(acc[i][0], ad, bp0);
                fma2(acc[i][1], ad, bp1);
                fma2(acc[i][2], ad, bp2);
                fma2(acc[i][3], ad, bp3);
            }
        }
    }

    const float4 bv0 = *(const float4*)(bias + n0 + tx * 8);
    const float4 bv1 = *(const float4*)(bias + n0 + tx * 8 + 4);
#pragma unroll
    for (int i = 0; i < 8; ++i) {
        const float2 c0 = unpack2(acc[i][0]);
        const float2 c1 = unpack2(acc[i][1]);
        const float2 c2 = unpack2(acc[i][2]);
        const float2 c3 = unpack2(acc[i][3]);
        const float4 o0 = make_float4(c0.x + bv0.x, c0.y + bv0.y, c1.x + bv0.z, c1.y + bv0.w);
        const float4 o1 = make_float4(c2.x + bv1.x, c2.y + bv1.y, c3.x + bv1.z, c3.y + bv1.w);
        float* crow = Cc + (size_t)(m0 + ty * 8 + i) * N + n0 + tx * 8;
        *(float4*)crow       = o0;
        *(float4*)(crow + 4) = o1;
    }
}

__global__ void __launch_bounds__(256, 2)
k_gemm_qkv(const float* __restrict__ X, const float* __restrict__ W,
           const float* __restrict__ bias) {
    gemm_tile(X, W, bias, g_qkv, N3C, C_);
}

__global__ void __launch_bounds__(256, 2)
k_gemm_proj(const float* __restrict__ W, const float* __restrict__ bias,
            float* __restrict__ out) {
    gemm_tile(g_y, W, bias, out, C_, C_);
}

// ---------------------------------------------------------------------------
// Flash attention, fp32. Grid (T/64, B*NH), 128 threads (8 ty x 16 tx).
// Per thread: 8 query rows x 4 key cols. Shared: Qs | K^T(swizzled)->P | V (48KB).
// K^T swizzle (float4 granularity): phys(d,c) = d*64 + (((c>>2)^(d&15))<<2) + (c&3)
//   -> S-loop float4 reads at (d, 4*tx) hit 16 distinct 16B chunks: conflict-free.
// ---------------------------------------------------------------------------
__global__ void __launch_bounds__(128, 3) k_attn() {
    __shared__ float Qs[64 * 64];
    __shared__ float KPs[64 * 64];   // K^T (swizzled) then reused for P
    __shared__ float Vs[64 * 64];

    const int tid = threadIdx.x;
    const int tx  = tid & 15;
    const int ty  = tid >> 4;          // 0..7
    const int qb  = blockIdx.x * 64;
    const int bh  = blockIdx.y;
    const int b   = bh >> 4;
    const int h   = bh & 15;

    const float* qbase = g_qkv + (size_t)b * T_ * N3C + h * HD_;
    const float* kbase = qbase + C_;
    const float* vbase = qbase + 2 * C_;

    const float scale = 0.125f;   // 1/sqrt(64), folded into Q

    // load Q tile (scaled). 64 rows x 64 dims, float4 per (row, 16B chunk)
#pragma unroll
    for (int it = 0; it < 8; ++it) {
        const int idx = it * 128 + tid;
        const int r  = idx >> 4;
        const int dg = (idx & 15) << 2;
        float4 v = *(const float4*)(qbase + (size_t)(qb + r) * N3C + dg);
        v.x *= scale; v.y *= scale; v.z *= scale; v.w *= scale;
        *(float4*)&Qs[r * 64 + dg] = v;
    }

    float m_i[8], l_i[8];
    ull o2[8][2];
#pragma unroll
    for (int r = 0; r < 8; ++r) {
        m_i[r] = -1e30f; l_i[r] = 0.f;
        o2[r][0] = 0ull; o2[r][1] = 0ull;
    }

    const int njt = blockIdx.x + 1;   // causal: only KV tiles with jb <= qb
    for (int j = 0; j < njt; ++j) {
        const int jb = j * 64;

        // load K transposed+swizzled, V natural
#pragma unroll
        for (int it = 0; it < 8; ++it) {
            const int idx = it * 128 + tid;
            const int r  = idx >> 4;
            const int dg = (idx & 15) << 2;
            F4U kv; kv.f = *(const float4*)(kbase + (size_t)(jb + r) * N3C + dg);
            const int rq = r >> 2, rb = r & 3;
#pragma unroll
            for (int i = 0; i < 4; ++i) {
                const int d = dg + i;
                KPs[d * 64 + ((rq ^ (d & 15)) << 2) + rb] = kv.a[i];
            }
            const float4 vv = *(const float4*)(vbase + (size_t)(jb + r) * N3C + dg);
            *(float4*)&Vs[r * 64 + dg] = vv;
        }
        __syncthreads();

        // S = Q @ K^T : rows ty*8..+7, cols tx*4..+3 (as 2 f32x2)
        ull s2[8][2];
#pragma unroll
        for (int r = 0; r < 8; ++r) { s2[r][0] = 0ull; s2[r][1] = 0ull; }

        for (int d0 = 0; d0 < 64; d0 += 4) {
            F4U kf[4];
#pragma unroll
            for (int dd = 0; dd < 4; ++dd) {
                const int d = d0 + dd;
                kf[dd].f = *(const float4*)&KPs[d * 64 + ((tx ^ (d & 15)) << 2)];
            }
#pragma unroll
            for (int r = 0; r < 8; ++r) {
                F4U qf; qf.f = *(const float4*)&Qs[(ty * 8 + r) * 64 + d0];
#pragma unroll
                for (int dd = 0; dd < 4; ++dd) {
                    const ull ad = pack2(qf.a[dd], qf.a[dd]);
                    fma2(s2[r][0], ad, kf[dd].p[0]);
                    fma2(s2[r][1], ad, kf[dd].p[1]);
                }
            }
        }

        float sf[8][4];
#pragma unroll
        for (int r = 0; r < 8; ++r) {
            const float2 p0 = unpack2(s2[r][0]);
            const float2 p1 = unpack2(s2[r][1]);
            sf[r][0] = p0.x; sf[r][1] = p0.y; sf[r][2] = p1.x; sf[r][3] = p1.y;
        }

        // causal mask: only the diagonal tile (jb == qb) has col > row entries
        if (j == njt - 1) {
#pragma unroll
            for (int r = 0; r < 8; ++r) {
                const int rloc = ty * 8 + r;
#pragma unroll
                for (int w = 0; w < 4; ++w)
                    if (tx * 4 + w > rloc) sf[r][w] = -1e30f;
            }
        }

        // online softmax (16-lane row groups; xor<16 stays within group)
#pragma unroll
        for (int r = 0; r < 8; ++r) {
            float mt = fmaxf(fmaxf(sf[r][0], sf[r][1]), fmaxf(sf[r][2], sf[r][3]));
#pragma unroll
            for (int off = 8; off > 0; off >>= 1)
                mt = fmaxf(mt, __shfl_xor_sync(0xffffffffu, mt, off));
            const float mnew = fmaxf(m_i[r], mt);
            const float corr = __expf(m_i[r] - mnew);
            m_i[r] = mnew;
            float rs = 0.f;
#pragma unroll
            for (int w = 0; w < 4; ++w) {
                sf[r][w] = __expf(sf[r][w] - mnew);
                rs += sf[r][w];
            }
#pragma unroll
            for (int off = 8; off > 0; off >>= 1)
                rs += __shfl_xor_sync(0xffffffffu, rs, off);
            l_i[r] = l_i[r] * corr + rs;
            const ull cd = pack2(corr, corr);
            o2[r][0] = mul2(o2[r][0], cd);
            o2[r][1] = mul2(o2[r][1], cd);
        }

        __syncthreads();   // everyone done reading K^T from KPs

        // write P (natural layout, contiguous float4 stores)
#pragma unroll
        for (int r = 0; r < 8; ++r) {
            *(float4*)&KPs[(ty * 8 + r) * 64 + tx * 4] =
                make_float4(sf[r][0], sf[r][1], sf[r][2], sf[r][3]);
        }
        __syncthreads();

        // O += P @ V : rows ty*8..+7, head dims tx*4..+3
        for (int c0 = 0; c0 < 64; c0 += 4) {
            F4U vf[4];
#pragma unroll
            for (int cc = 0; cc < 4; ++cc)
                vf[cc].f = *(const float4*)&Vs[(c0 + cc) * 64 + tx * 4];
#pragma unroll
            for (int r = 0; r < 8; ++r) {
                F4U pf; pf.f = *(const float4*)&KPs[(ty * 8 + r) * 64 + c0];
#pragma unroll
                for (int cc = 0; cc < 4; ++cc) {
                    const ull ad = pack2(pf.a[cc], pf.a[cc]);
                    fma2(o2[r][0], ad, vf[cc].p[0]);
                    fma2(o2[r][1], ad, vf[cc].p[1]);
                }
            }
        }
        __syncthreads();   // before next tile overwrites KPs/Vs
    }

    // epilogue: normalize and store to [B,T,C] layout
#pragma unroll
    for (int r = 0; r < 8; ++r) {
        const float inv = 1.0f / l_i[r];
        const float2 p0 = unpack2(o2[r][0]);
        const float2 p1 = unpack2(o2[r][1]);
        const float4 o = make_float4(p0.x * inv, p0.y * inv, p1.x * inv, p1.y * inv);
        const int row = qb + ty * 8 + r;
        *(float4*)(g_y + (size_t)(b * T_ + row) * C_ + h * HD_ + tx * 4) = o;
    }
}

// ---------------------------------------------------------------------------
extern "C" void kernel_launch(void* const* d_in, const int* in_sizes, int n_in,
                              void* d_out, int out_size) {
    const float* x  = (const float*)d_in[0];  // [4,2048,1024]
    const float* Wa = (const float*)d_in[1];  // [1024,3072]
    const float* ba = (const float*)d_in[2];  // [3072]
    const float* Wp = (const float*)d_in[3];  // [1024,1024]
    const float* bp = (const float*)d_in[4];  // [1024]
    float* out = (float*)d_out;               // [4,2048,1024]

    (void)in_sizes; (void)n_in; (void)out_size;

    k_gemm_qkv <<<dim3(N3C / GBN, M_ / GBM), 256>>>(x, Wa, ba);   // (24, 64)
    k_attn     <<<dim3(T_ / 64, B_ * NH_), 128>>>();              // (32, 64)
    k_gemm_proj<<<dim3(C_ / GBN, M_ / GBM), 256>>>(Wp, bp, out);  // (8, 64)
}

// round 16
// speedup vs baseline: 1.5199x; 1.5199x over previous
#include <cuda_runtime.h>
#include <cuda_bf16.h>
#include <cstdint>
#include <cstddef>

// ---------------------------------------------------------------------------
// CausalSelfAttention on GB300 (sm_103a, base-target ISA: mma.sync bf16)
//  Stage 0: split x -> bf16 (hi,lo); split+transpose W_attn/W_proj -> bf16 (hi,lo) [N,K]
//  Stage 1: QKV GEMM via mma.sync.m16n8k16 bf16 (split-2, 3 cross MMAs) -> g_qkv fp32
//  Stage 2: flash attention fp32 (FFMA2) -> y emitted as bf16 (hi,lo)
//  Stage 3: proj GEMM via mma.sync -> d_out fp32
//
//  CRITICAL RULE (GB300/ATS pitfall): device globals are NEVER passed as
//  kernel arguments from host code — host-side references to __device__
//  symbols yield the HOST shadow address, which ATS happily dereferences
//  (reading zeros) instead of faulting. All global bindings happen in
//  device code via a `which` selector.
// ---------------------------------------------------------------------------

typedef unsigned long long ull;

#define B_  4
#define T_  2048
#define C_  1024
#define NH_ 16
#define HD_ 64
#define M_  (B_ * T_)   // 8192
#define N3C (3 * C_)    // 3072

// scratch (static device globals: allocation-guard safe)
__device__ float          g_qkv[(size_t)M_ * N3C];   // fp32 [8192,3072]
__device__ __nv_bfloat16  g_xh [(size_t)M_ * C_];
__device__ __nv_bfloat16  g_xl [(size_t)M_ * C_];
__device__ __nv_bfloat16  g_wah[(size_t)N3C * C_];   // W_attn^T split, [3072,1024]
__device__ __nv_bfloat16  g_wal[(size_t)N3C * C_];
__device__ __nv_bfloat16  g_wph[(size_t)C_ * C_];    // W_proj^T split, [1024,1024]
__device__ __nv_bfloat16  g_wpl[(size_t)C_ * C_];
__device__ __nv_bfloat16  g_yh [(size_t)M_ * C_];    // attention out split
__device__ __nv_bfloat16  g_yl [(size_t)M_ * C_];

// ---------------------------------------------------------------------------
__device__ __forceinline__ uint32_t smem_to_u32(const void* p) {
    uint32_t a;
    asm("{ .reg .u64 t; cvta.to.shared.u64 t, %1; cvt.u32.u64 %0, t; }" : "=r"(a) : "l"(p));
    return a;
}
__device__ __forceinline__ void ldm4(uint32_t& r0, uint32_t& r1, uint32_t& r2,
                                     uint32_t& r3, uint32_t a) {
    asm volatile("ldmatrix.sync.aligned.m8n8.x4.shared.b16 {%0,%1,%2,%3}, [%4];"
        : "=r"(r0), "=r"(r1), "=r"(r2), "=r"(r3) : "r"(a));
}
__device__ __forceinline__ void mma16816(float* d, const uint32_t* a, const uint32_t* b) {
    asm volatile("mma.sync.aligned.m16n8k16.row.col.f32.bf16.bf16.f32 "
        "{%0,%1,%2,%3}, {%4,%5,%6,%7}, {%8,%9}, {%0,%1,%2,%3};"
        : "+f"(d[0]), "+f"(d[1]), "+f"(d[2]), "+f"(d[3])
        : "r"(a[0]), "r"(a[1]), "r"(a[2]), "r"(a[3]), "r"(b[0]), "r"(b[1]));
}

// FFMA2 helpers (attention)
union F4U { float4 f; float a[4]; ull p[2]; };
__device__ __forceinline__ ull pack2(float x, float y) {
    ull r; asm("mov.b64 %0, {%1, %2};" : "=l"(r) : "f"(x), "f"(y)); return r;
}
__device__ __forceinline__ float2 unpack2(ull v) {
    float2 r; asm("mov.b64 {%0, %1}, %2;" : "=f"(r.x), "=f"(r.y) : "l"(v)); return r;
}
__device__ __forceinline__ void fma2(ull& d, ull a, ull b) {
    asm("fma.rn.f32x2 %0, %1, %2, %0;" : "+l"(d) : "l"(a), "l"(b));
}
__device__ __forceinline__ ull mul2(ull a, ull b) {
    ull d; asm("mul.rn.f32x2 %0, %1, %2;" : "=l"(d) : "l"(a), "l"(b)); return d;
}

// ---------------------------------------------------------------------------
// Stage 0: precision splits (globals referenced DEVICE-side only)
// ---------------------------------------------------------------------------
__global__ void __launch_bounds__(256) k_split_x(const float* __restrict__ x) {
    const size_t i = ((size_t)blockIdx.x * 256 + threadIdx.x) * 4;
    const float4 v = *(const float4*)(x + i);
    const float vv[4] = {v.x, v.y, v.z, v.w};
    union { __nv_bfloat16 b[4]; uint2 u; } h, l;
#pragma unroll
    for (int w = 0; w < 4; ++w) {
        const __nv_bfloat16 hb = __float2bfloat16(vv[w]);
        h.b[w] = hb;
        l.b[w] = __float2bfloat16(vv[w] - __bfloat162float(hb));
    }
    *(uint2*)(g_xh + i) = h.u;
    *(uint2*)(g_xl + i) = l.u;
}

// W [K=1024, N] row-major -> Wh/Wl [N,1024] transposed bf16 hi/lo.
// which: 0 = W_attn -> g_wah/g_wal (N=3072), 1 = W_proj -> g_wph/g_wpl (N=1024)
__global__ void __launch_bounds__(256) k_split_wT(const float* __restrict__ W,
                                                  int which, int N) {
    __nv_bfloat16* __restrict__ Wh = which ? g_wph : g_wah;
    __nv_bfloat16* __restrict__ Wl = which ? g_wpl : g_wal;
    __shared__ float t[32][33];
    const int tx = threadIdx.x & 31;
    const int ty = threadIdx.x >> 5;      // 0..7
    const int n0 = blockIdx.x * 32;
    const int k0 = blockIdx.y * 32;
#pragma unroll
    for (int i = 0; i < 4; ++i)
        t[ty + 8 * i][tx] = W[(size_t)(k0 + ty + 8 * i) * N + n0 + tx];
    __syncthreads();
#pragma unroll
    for (int i = 0; i < 4; ++i) {
        const float v = t[tx][ty + 8 * i];
        const __nv_bfloat16 hb = __float2bfloat16(v);
        const size_t o = (size_t)(n0 + ty + 8 * i) * C_ + k0 + tx;
        Wh[o] = hb;
        Wl[o] = __float2bfloat16(v - __bfloat162float(hb));
    }
}

// ---------------------------------------------------------------------------
// bf16 mma.sync GEMM: C[m][n] = sum_k A[m][k]*B[n][k] + bias[n]
// which: 0 = QKV (A=g_xh/l, B=g_wah/l, C=g_qkv, N=3072)
//        1 = proj (A=g_yh/l, B=g_wph/l, C=Cout,  N=1024)
// CTA 128x128, BK=32, 8 warps (2m x 4n), warp tile 64x32 (4x4 m16n8 tiles).
// smem: 4 regions x 128 rows x 80B = 40KB static; reg-prefetch pipeline.
// ---------------------------------------------------------------------------
#define GSTRIDE  80
#define REG_SZ   (128 * GSTRIDE)   // 10240
#define STAGE_SZ (4 * REG_SZ)      // 40960 static

__global__ void __launch_bounds__(256, 1)
k_gemm_mma(const float* __restrict__ bias, float* __restrict__ Cout,
           int which, int N) {
    const __nv_bfloat16* __restrict__ Ah = which ? g_yh : g_xh;
    const __nv_bfloat16* __restrict__ Al = which ? g_yl : g_xl;
    const __nv_bfloat16* __restrict__ Bh = which ? g_wph : g_wah;
    const __nv_bfloat16* __restrict__ Bl = which ? g_wpl : g_wal;
    float* __restrict__ Cc = which ? Cout : g_qkv;

    __shared__ __align__(16) char sm[STAGE_SZ];
    const uint32_t sbase = smem_to_u32(sm);
    const int tid  = threadIdx.x;
    const int lane = tid & 31;
    const int wid  = tid >> 5;
    const int wm   = (wid & 1) * 64;
    const int wn   = (wid >> 1) * 32;
    const int m0   = blockIdx.y * 128;
    const int n0   = blockIdx.x * 128;

    const __nv_bfloat16* srcs[4] = {
        Ah + (size_t)m0 * C_, Al + (size_t)m0 * C_,
        Bh + (size_t)n0 * C_, Bl + (size_t)n0 * C_ };

    const int lrow = tid >> 2;       // 0..63
    const int lq   = tid & 3;        // 16B quad within 64B row

    // preload chunk 0
#pragma unroll
    for (int g = 0; g < 4; ++g)
#pragma unroll
        for (int t = 0; t < 2; ++t) {
            const int r = lrow + t * 64;
            const uint4 v = *(const uint4*)(srcs[g] + (size_t)r * C_ + lq * 8);
            *(uint4*)(sm + g * REG_SZ + r * GSTRIDE + lq * 16) = v;
        }
    __syncthreads();

    float d[4][4][4];
#pragma unroll
    for (int mi = 0; mi < 4; ++mi)
#pragma unroll
        for (int ni = 0; ni < 4; ++ni)
#pragma unroll
            for (int q = 0; q < 4; ++q) d[mi][ni][q] = 0.f;

    // ldmatrix per-lane addressing
    const int a_m = (lane & 7) + ((lane >> 3) & 1) * 8;  // lane%16 -> m row
    const int a_k = (lane >> 4) * 8;                     // k half
    const int b_r = (lane & 7) + ((lane >> 4) << 3);     // n row
    const int b_k = ((lane >> 3) & 1) * 8;               // k half

    const int NCH = C_ / 32;   // 32 chunks
    for (int c = 0; c < NCH; ++c) {
        const bool more = (c + 1 < NCH);
        uint4 pre[4][2];
        if (more) {
            const int kc2 = (c + 1) * 32;
#pragma unroll
            for (int g = 0; g < 4; ++g)
#pragma unroll
                for (int t = 0; t < 2; ++t) {
                    const int r = lrow + t * 64;
                    pre[g][t] = *(const uint4*)(srcs[g] + (size_t)r * C_ + kc2 + lq * 8);
                }
        }
        // compute chunk c out of smem (overlaps in-flight prefetch LDGs)
#pragma unroll
        for (int ks = 0; ks < 2; ++ks) {
            uint32_t ah[4][4], al[4][4], bh[4][2], bl[4][2];
#pragma unroll
            for (int mi = 0; mi < 4; ++mi) {
                const uint32_t ad = sbase + (wm + mi * 16 + a_m) * GSTRIDE + (ks * 16 + a_k) * 2;
                ldm4(ah[mi][0], ah[mi][1], ah[mi][2], ah[mi][3], ad);
                ldm4(al[mi][0], al[mi][1], al[mi][2], al[mi][3], ad + REG_SZ);
            }
#pragma unroll
            for (int p = 0; p < 2; ++p) {
                const uint32_t bd = sbase + 2 * REG_SZ
                    + (wn + 16 * p + b_r) * GSTRIDE + (ks * 16 + b_k) * 2;
                ldm4(bh[2 * p][0], bh[2 * p][1], bh[2 * p + 1][0], bh[2 * p + 1][1], bd);
                ldm4(bl[2 * p][0], bl[2 * p][1], bl[2 * p + 1][0], bl[2 * p + 1][1], bd + REG_SZ);
            }
#pragma unroll
            for (int mi = 0; mi < 4; ++mi)
#pragma unroll
                for (int ni = 0; ni < 4; ++ni) {
                    mma16816(d[mi][ni], ah[mi], bh[ni]);   // hi*hi
                    mma16816(d[mi][ni], ah[mi], bl[ni]);   // hi*lo
                    mma16816(d[mi][ni], al[mi], bh[ni]);   // lo*hi
                }
        }
        if (more) {
            __syncthreads();   // all warps done reading chunk c
#pragma unroll
            for (int g = 0; g < 4; ++g)
#pragma unroll
                for (int t = 0; t < 2; ++t) {
                    const int r = lrow + t * 64;
                    *(uint4*)(sm + g * REG_SZ + r * GSTRIDE + lq * 16) = pre[g][t];
                }
            __syncthreads();   // chunk c+1 visible
        }
    }

    // epilogue: d[mi][ni]: rows (lane/4, +8), cols (lane%4)*2..+1
    const int rr  = lane >> 2;
    const int cc2 = (lane & 3) * 2;
#pragma unroll
    for (int ni = 0; ni < 4; ++ni) {
        const int col = n0 + wn + ni * 8 + cc2;
        const float2 bv = *(const float2*)(bias + col);
#pragma unroll
        for (int mi = 0; mi < 4; ++mi) {
            const int r0 = m0 + wm + mi * 16 + rr;
            float2 o0 = make_float2(d[mi][ni][0] + bv.x, d[mi][ni][1] + bv.y);
            float2 o1 = make_float2(d[mi][ni][2] + bv.x, d[mi][ni][3] + bv.y);
            *(float2*)(Cc + (size_t)r0 * N + col)       = o0;
            *(float2*)(Cc + (size_t)(r0 + 8) * N + col) = o1;
        }
    }
}

// ---------------------------------------------------------------------------
// Flash attention, fp32 FFMA2 (proven in R8). Grid (T/64, B*NH), 128 threads.
// Epilogue emits y as bf16 (hi,lo) for the mma proj GEMM.
// ---------------------------------------------------------------------------
__global__ void __launch_bounds__(128, 3) k_attn() {
    __shared__ float Qs[64 * 64];
    __shared__ float KPs[64 * 64];   // K^T (swizzled) then reused for P
    __shared__ float Vs[64 * 64];

    const int tid = threadIdx.x;
    const int tx  = tid & 15;
    const int ty  = tid >> 4;
    const int qb  = blockIdx.x * 64;
    const int bh  = blockIdx.y;
    const int b   = bh >> 4;
    const int h   = bh & 15;

    const float* qbase = g_qkv + (size_t)b * T_ * N3C + h * HD_;
    const float* kbase = qbase + C_;
    const float* vbase = qbase + 2 * C_;

    const float scale = 0.125f;

#pragma unroll
    for (int it = 0; it < 8; ++it) {
        const int idx = it * 128 + tid;
        const int r  = idx >> 4;
        const int dg = (idx & 15) << 2;
        float4 v = *(const float4*)(qbase + (size_t)(qb + r) * N3C + dg);
        v.x *= scale; v.y *= scale; v.z *= scale; v.w *= scale;
        *(float4*)&Qs[r * 64 + dg] = v;
    }

    float m_i[8], l_i[8];
    ull o2[8][2];
#pragma unroll
    for (int r = 0; r < 8; ++r) {
        m_i[r] = -1e30f; l_i[r] = 0.f;
        o2[r][0] = 0ull; o2[r][1] = 0ull;
    }

    const int njt = blockIdx.x + 1;
    for (int j = 0; j < njt; ++j) {
        const int jb = j * 64;
#pragma unroll
        for (int it = 0; it < 8; ++it) {
            const int idx = it * 128 + tid;
            const int r  = idx >> 4;
            const int dg = (idx & 15) << 2;
            F4U kv; kv.f = *(const float4*)(kbase + (size_t)(jb + r) * N3C + dg);
            const int rq = r >> 2, rb = r & 3;
#pragma unroll
            for (int i = 0; i < 4; ++i) {
                const int d = dg + i;
                KPs[d * 64 + ((rq ^ (d & 15)) << 2) + rb] = kv.a[i];
            }
            const float4 vv = *(const float4*)(vbase + (size_t)(jb + r) * N3C + dg);
            *(float4*)&Vs[r * 64 + dg] = vv;
        }
        __syncthreads();

        ull s2[8][2];
#pragma unroll
        for (int r = 0; r < 8; ++r) { s2[r][0] = 0ull; s2[r][1] = 0ull; }

        for (int d0 = 0; d0 < 64; d0 += 4) {
            F4U kf[4];
#pragma unroll
            for (int dd = 0; dd < 4; ++dd) {
                const int d = d0 + dd;
                kf[dd].f = *(const float4*)&KPs[d * 64 + ((tx ^ (d & 15)) << 2)];
            }
#pragma unroll
            for (int r = 0; r < 8; ++r) {
                F4U qf; qf.f = *(const float4*)&Qs[(ty * 8 + r) * 64 + d0];
#pragma unroll
                for (int dd = 0; dd < 4; ++dd) {
                    const ull ad = pack2(qf.a[dd], qf.a[dd]);
                    fma2(s2[r][0], ad, kf[dd].p[0]);
                    fma2(s2[r][1], ad, kf[dd].p[1]);
                }
            }
        }

        float sf[8][4];
#pragma unroll
        for (int r = 0; r < 8; ++r) {
            const float2 p0 = unpack2(s2[r][0]);
            const float2 p1 = unpack2(s2[r][1]);
            sf[r][0] = p0.x; sf[r][1] = p0.y; sf[r][2] = p1.x; sf[r][3] = p1.y;
        }

        if (j == njt - 1) {
#pragma unroll
            for (int r = 0; r < 8; ++r) {
                const int rloc = ty * 8 + r;
#pragma unroll
                for (int w = 0; w < 4; ++w)
                    if (tx * 4 + w > rloc) sf[r][w] = -1e30f;
            }
        }

#pragma unroll
        for (int r = 0; r < 8; ++r) {
            float mt = fmaxf(fmaxf(sf[r][0], sf[r][1]), fmaxf(sf[r][2], sf[r][3]));
#pragma unroll
            for (int off = 8; off > 0; off >>= 1)
                mt = fmaxf(mt, __shfl_xor_sync(0xffffffffu, mt, off));
            const float mnew = fmaxf(m_i[r], mt);
            const float corr = __expf(m_i[r] - mnew);
            m_i[r] = mnew;
            float rs = 0.f;
#pragma unroll
            for (int w = 0; w < 4; ++w) {
                sf[r][w] = __expf(sf[r][w] - mnew);
                rs += sf[r][w];
            }
#pragma unroll
            for (int off = 8; off > 0; off >>= 1)
                rs += __shfl_xor_sync(0xffffffffu, rs, off);
            l_i[r] = l_i[r] * corr + rs;
            const ull cd = pack2(corr, corr);
            o2[r][0] = mul2(o2[r][0], cd);
            o2[r][1] = mul2(o2[r][1], cd);
        }

        __syncthreads();
#pragma unroll
        for (int r = 0; r < 8; ++r) {
            *(float4*)&KPs[(ty * 8 + r) * 64 + tx * 4] =
                make_float4(sf[r][0], sf[r][1], sf[r][2], sf[r][3]);
        }
        __syncthreads();

        for (int c0 = 0; c0 < 64; c0 += 4) {
            F4U vf[4];
#pragma unroll
            for (int cc = 0; cc < 4; ++cc)
                vf[cc].f = *(const float4*)&Vs[(c0 + cc) * 64 + tx * 4];
#pragma unroll
            for (int r = 0; r < 8; ++r) {
                F4U pf; pf.f = *(const float4*)&KPs[(ty * 8 + r) * 64 + c0];
#pragma unroll
                for (int cc = 0; cc < 4; ++cc) {
                    const ull ad = pack2(pf.a[cc], pf.a[cc]);
                    fma2(o2[r][0], ad, vf[cc].p[0]);
                    fma2(o2[r][1], ad, vf[cc].p[1]);
                }
            }
        }
        __syncthreads();
    }

    // epilogue: normalize, split to bf16 hi/lo for the mma proj GEMM
#pragma unroll
    for (int r = 0; r < 8; ++r) {
        const float inv = 1.0f / l_i[r];
        const float2 p0 = unpack2(o2[r][0]);
        const float2 p1 = unpack2(o2[r][1]);
        const float ov[4] = {p0.x * inv, p0.y * inv, p1.x * inv, p1.y * inv};
        union { __nv_bfloat16 bb[4]; uint2 u; } hh, ll;
#pragma unroll
        for (int w = 0; w < 4; ++w) {
            const __nv_bfloat16 hb = __float2bfloat16(ov[w]);
            hh.bb[w] = hb;
            ll.bb[w] = __float2bfloat16(ov[w] - __bfloat162float(hb));
        }
        const int row = qb + ty * 8 + r;
        const size_t off = (size_t)(b * T_ + row) * C_ + h * HD_ + tx * 4;
        *(uint2*)(g_yh + off) = hh.u;
        *(uint2*)(g_yl + off) = ll.u;
    }
}

// ---------------------------------------------------------------------------
extern "C" void kernel_launch(void* const* d_in, const int* in_sizes, int n_in,
                              void* d_out, int out_size) {
    const float* x  = (const float*)d_in[0];  // [4,2048,1024]
    const float* Wa = (const float*)d_in[1];  // [1024,3072]
    const float* ba = (const float*)d_in[2];  // [3072]
    const float* Wp = (const float*)d_in[3];  // [1024,1024]
    const float* bp = (const float*)d_in[4];  // [1024]
    float* out = (float*)d_out;               // [4,2048,1024]
    (void)in_sizes; (void)n_in; (void)out_size;

    // Stage 0: splits (only harness pointers cross the launch boundary)
    k_split_x  <<<(M_ * C_) / 1024, 256>>>(x);
    k_split_wT <<<dim3(N3C / 32, C_ / 32), 256>>>(Wa, 0, N3C);
    k_split_wT <<<dim3(C_ / 32,  C_ / 32), 256>>>(Wp, 1, C_);

    // Stage 1: QKV GEMM (mma.sync bf16 split-2) -> g_qkv (bound device-side)
    k_gemm_mma <<<dim3(N3C / 128, M_ / 128), 256>>>(ba, nullptr, 0, N3C);

    // Stage 2: attention (globals device-side)
    k_attn     <<<dim3(T_ / 64, B_ * NH_), 128>>>();

    // Stage 3: projection GEMM -> d_out
    k_gemm_mma <<<dim3(C_ / 128, M_ / 128), 256>>>(bp, out, 1, C_);
}

// round 17
// speedup vs baseline: 2.0703x; 1.3622x over previous
#include <cuda_runtime.h>
#include <cuda_bf16.h>
#include <cstdint>
#include <cstddef>

// ---------------------------------------------------------------------------
// CausalSelfAttention on GB300 (sm_103a, base-target ISA: mma.sync bf16)
//  Stage 0: split x -> bf16 (hi,lo); split+transpose W_attn/W_proj -> bf16 (hi,lo)
//  Stage 1: QKV GEMM via mma.sync.m16n8k16 bf16 (split-2) -> g_qkv fp32
//  Stage 2: flash attention, NOW on mma.sync bf16 split-2 as well:
//           S = (Qh+Ql)(Kh+Kl)^T, P repacked from C-frags to A-frags in regs,
//           O += (Ph+Pl)(Vh+Vl) with V transposed in smem. fp32 softmax.
//  Stage 3: proj GEMM via mma.sync -> d_out fp32
//
//  CRITICAL RULE (GB300/ATS pitfall): device globals are NEVER passed as
//  kernel arguments from host code (host shadow address + ATS reads zeros).
//  All global bindings happen in device code via a `which` selector.
// ---------------------------------------------------------------------------

typedef unsigned long long ull;

#define B_  4
#define T_  2048
#define C_  1024
#define NH_ 16
#define HD_ 64
#define M_  (B_ * T_)   // 8192
#define N3C (3 * C_)    // 3072

// scratch (static device globals: allocation-guard safe)
__device__ float          g_qkv[(size_t)M_ * N3C];   // fp32 [8192,3072]
__device__ __nv_bfloat16  g_xh [(size_t)M_ * C_];
__device__ __nv_bfloat16  g_xl [(size_t)M_ * C_];
__device__ __nv_bfloat16  g_wah[(size_t)N3C * C_];   // W_attn^T split, [3072,1024]
__device__ __nv_bfloat16  g_wal[(size_t)N3C * C_];
__device__ __nv_bfloat16  g_wph[(size_t)C_ * C_];    // W_proj^T split, [1024,1024]
__device__ __nv_bfloat16  g_wpl[(size_t)C_ * C_];
__device__ __nv_bfloat16  g_yh [(size_t)M_ * C_];    // attention out split
__device__ __nv_bfloat16  g_yl [(size_t)M_ * C_];

// ---------------------------------------------------------------------------
__device__ __forceinline__ uint32_t smem_to_u32(const void* p) {
    uint32_t a;
    asm("{ .reg .u64 t; cvta.to.shared.u64 t, %1; cvt.u32.u64 %0, t; }" : "=r"(a) : "l"(p));
    return a;
}
__device__ __forceinline__ void ldm4(uint32_t& r0, uint32_t& r1, uint32_t& r2,
                                     uint32_t& r3, uint32_t a) {
    asm volatile("ldmatrix.sync.aligned.m8n8.x4.shared.b16 {%0,%1,%2,%3}, [%4];"
        : "=r"(r0), "=r"(r1), "=r"(r2), "=r"(r3) : "r"(a));
}
__device__ __forceinline__ void mma16816(float* d, const uint32_t* a, const uint32_t* b) {
    asm volatile("mma.sync.aligned.m16n8k16.row.col.f32.bf16.bf16.f32 "
        "{%0,%1,%2,%3}, {%4,%5,%6,%7}, {%8,%9}, {%0,%1,%2,%3};"
        : "+f"(d[0]), "+f"(d[1]), "+f"(d[2]), "+f"(d[3])
        : "r"(a[0]), "r"(a[1]), "r"(a[2]), "r"(a[3]), "r"(b[0]), "r"(b[1]));
}

// split a pair of fp32 into packed bf16 hi (lo-lane=a) and packed bf16 lo-residual
__device__ __forceinline__ void split2(float a, float b, uint32_t& hp, uint32_t& lp) {
    const __nv_bfloat16 ha = __float2bfloat16(a), hb = __float2bfloat16(b);
    const float ra = a - __bfloat162float(ha), rb = b - __bfloat162float(hb);
    const __nv_bfloat16 la = __float2bfloat16(ra), lb = __float2bfloat16(rb);
    hp = (uint32_t)__bfloat16_as_ushort(ha) | ((uint32_t)__bfloat16_as_ushort(hb) << 16);
    lp = (uint32_t)__bfloat16_as_ushort(la) | ((uint32_t)__bfloat16_as_ushort(lb) << 16);
}

// ---------------------------------------------------------------------------
// Stage 0: precision splits (globals referenced DEVICE-side only)
// ---------------------------------------------------------------------------
__global__ void __launch_bounds__(256) k_split_x(const float* __restrict__ x) {
    const size_t i = ((size_t)blockIdx.x * 256 + threadIdx.x) * 4;
    const float4 v = *(const float4*)(x + i);
    uint32_t h0, l0, h1, l1;
    split2(v.x, v.y, h0, l0);
    split2(v.z, v.w, h1, l1);
    *(uint2*)(g_xh + i) = make_uint2(h0, h1);
    *(uint2*)(g_xl + i) = make_uint2(l0, l1);
}

// W [K=1024, N] row-major -> Wh/Wl [N,1024] transposed bf16 hi/lo.
// which: 0 = W_attn -> g_wah/g_wal (N=3072), 1 = W_proj -> g_wph/g_wpl (N=1024)
__global__ void __launch_bounds__(256) k_split_wT(const float* __restrict__ W,
                                                  int which, int N) {
    __nv_bfloat16* __restrict__ Wh = which ? g_wph : g_wah;
    __nv_bfloat16* __restrict__ Wl = which ? g_wpl : g_wal;
    __shared__ float t[32][33];
    const int tx = threadIdx.x & 31;
    const int ty = threadIdx.x >> 5;      // 0..7
    const int n0 = blockIdx.x * 32;
    const int k0 = blockIdx.y * 32;
#pragma unroll
    for (int i = 0; i < 4; ++i)
        t[ty + 8 * i][tx] = W[(size_t)(k0 + ty + 8 * i) * N + n0 + tx];
    __syncthreads();
#pragma unroll
    for (int i = 0; i < 4; ++i) {
        const float v = t[tx][ty + 8 * i];
        const __nv_bfloat16 hb = __float2bfloat16(v);
        const size_t o = (size_t)(n0 + ty + 8 * i) * C_ + k0 + tx;
        Wh[o] = hb;
        Wl[o] = __float2bfloat16(v - __bfloat162float(hb));
    }
}

// ---------------------------------------------------------------------------
// bf16 mma.sync GEMM (unchanged from R16, passing at rel_err 1.4e-5)
// ---------------------------------------------------------------------------
#define GSTRIDE  80
#define REG_SZ   (128 * GSTRIDE)   // 10240
#define STAGE_SZ (4 * REG_SZ)      // 40960 static

__global__ void __launch_bounds__(256, 1)
k_gemm_mma(const float* __restrict__ bias, float* __restrict__ Cout,
           int which, int N) {
    const __nv_bfloat16* __restrict__ Ah = which ? g_yh : g_xh;
    const __nv_bfloat16* __restrict__ Al = which ? g_yl : g_xl;
    const __nv_bfloat16* __restrict__ Bh = which ? g_wph : g_wah;
    const __nv_bfloat16* __restrict__ Bl = which ? g_wpl : g_wal;
    float* __restrict__ Cc = which ? Cout : g_qkv;

    __shared__ __align__(16) char sm[STAGE_SZ];
    const uint32_t sbase = smem_to_u32(sm);
    const int tid  = threadIdx.x;
    const int lane = tid & 31;
    const int wid  = tid >> 5;
    const int wm   = (wid & 1) * 64;
    const int wn   = (wid >> 1) * 32;
    const int m0   = blockIdx.y * 128;
    const int n0   = blockIdx.x * 128;

    const __nv_bfloat16* srcs[4] = {
        Ah + (size_t)m0 * C_, Al + (size_t)m0 * C_,
        Bh + (size_t)n0 * C_, Bl + (size_t)n0 * C_ };

    const int lrow = tid >> 2;
    const int lq   = tid & 3;

#pragma unroll
    for (int g = 0; g < 4; ++g)
#pragma unroll
        for (int t = 0; t < 2; ++t) {
            const int r = lrow + t * 64;
            const uint4 v = *(const uint4*)(srcs[g] + (size_t)r * C_ + lq * 8);
            *(uint4*)(sm + g * REG_SZ + r * GSTRIDE + lq * 16) = v;
        }
    __syncthreads();

    float d[4][4][4];
#pragma unroll
    for (int mi = 0; mi < 4; ++mi)
#pragma unroll
        for (int ni = 0; ni < 4; ++ni)
#pragma unroll
            for (int q = 0; q < 4; ++q) d[mi][ni][q] = 0.f;

    const int a_m = (lane & 7) + ((lane >> 3) & 1) * 8;
    const int a_k = (lane >> 4) * 8;
    const int b_r = (lane & 7) + ((lane >> 4) << 3);
    const int b_k = ((lane >> 3) & 1) * 8;

    const int NCH = C_ / 32;
    for (int c = 0; c < NCH; ++c) {
        const bool more = (c + 1 < NCH);
        uint4 pre[4][2];
        if (more) {
            const int kc2 = (c + 1) * 32;
#pragma unroll
            for (int g = 0; g < 4; ++g)
#pragma unroll
                for (int t = 0; t < 2; ++t) {
                    const int r = lrow + t * 64;
                    pre[g][t] = *(const uint4*)(srcs[g] + (size_t)r * C_ + kc2 + lq * 8);
                }
        }
#pragma unroll
        for (int ks = 0; ks < 2; ++ks) {
            uint32_t ah[4][4], al[4][4], bh[4][2], bl[4][2];
#pragma unroll
            for (int mi = 0; mi < 4; ++mi) {
                const uint32_t ad = sbase + (wm + mi * 16 + a_m) * GSTRIDE + (ks * 16 + a_k) * 2;
                ldm4(ah[mi][0], ah[mi][1], ah[mi][2], ah[mi][3], ad);
                ldm4(al[mi][0], al[mi][1], al[mi][2], al[mi][3], ad + REG_SZ);
            }
#pragma unroll
            for (int p = 0; p < 2; ++p) {
                const uint32_t bd = sbase + 2 * REG_SZ
                    + (wn + 16 * p + b_r) * GSTRIDE + (ks * 16 + b_k) * 2;
                ldm4(bh[2 * p][0], bh[2 * p][1], bh[2 * p + 1][0], bh[2 * p + 1][1], bd);
                ldm4(bl[2 * p][0], bl[2 * p][1], bl[2 * p + 1][0], bl[2 * p + 1][1], bd + REG_SZ);
            }
#pragma unroll
            for (int mi = 0; mi < 4; ++mi)
#pragma unroll
                for (int ni = 0; ni < 4; ++ni) {
                    mma16816(d[mi][ni], ah[mi], bh[ni]);
                    mma16816(d[mi][ni], ah[mi], bl[ni]);
                    mma16816(d[mi][ni], al[mi], bh[ni]);
                }
        }
        if (more) {
            __syncthreads();
#pragma unroll
            for (int g = 0; g < 4; ++g)
#pragma unroll
                for (int t = 0; t < 2; ++t) {
                    const int r = lrow + t * 64;
                    *(uint4*)(sm + g * REG_SZ + r * GSTRIDE + lq * 16) = pre[g][t];
                }
            __syncthreads();
        }
    }

    const int rr  = lane >> 2;
    const int cc2 = (lane & 3) * 2;
#pragma unroll
    for (int ni = 0; ni < 4; ++ni) {
        const int col = n0 + wn + ni * 8 + cc2;
        const float2 bv = *(const float2*)(bias + col);
#pragma unroll
        for (int mi = 0; mi < 4; ++mi) {
            const int r0 = m0 + wm + mi * 16 + rr;
            float2 o0 = make_float2(d[mi][ni][0] + bv.x, d[mi][ni][1] + bv.y);
            float2 o1 = make_float2(d[mi][ni][2] + bv.x, d[mi][ni][3] + bv.y);
            *(float2*)(Cc + (size_t)r0 * N + col)       = o0;
            *(float2*)(Cc + (size_t)(r0 + 8) * N + col) = o1;
        }
    }
}

// ---------------------------------------------------------------------------
// Flash attention on mma.sync bf16 split-2.
// Grid (T/64, B*NH), 128 threads = 4 warps; warp w owns query rows w*16..+15.
// smem: sA = Q(h,l) [64][72] -> reused as V^T(h,l) [hd=64][key 72-stride]
//       sB = K(h,l) [64][72]
// S accumulated fp32 in C-frags; P repacked C-frag -> A-frag in registers.
// ---------------------------------------------------------------------------
#define AST 72          // row stride (bf16 elems): 144B -> conflict-free ldmatrix
#define PLN (64 * AST)  // plane size (elems)

__global__ void __launch_bounds__(128, 3) k_attn() {
    __shared__ __align__(16) __nv_bfloat16 sA[2 * PLN];  // Qh,Ql -> Vth,Vtl
    __shared__ __align__(16) __nv_bfloat16 sB[2 * PLN];  // Kh,Kl

    const uint32_t sAu = smem_to_u32(sA);
    const uint32_t sBu = smem_to_u32(sB);
    const int tid  = threadIdx.x;
    const int lane = tid & 31;
    const int w    = tid >> 5;         // 0..3
    const int wm   = w * 16;
    const int qb   = blockIdx.x * 64;
    const int bh   = blockIdx.y;
    const int b    = bh >> 4;
    const int h    = bh & 15;

    const float* qbase = g_qkv + (size_t)b * T_ * N3C + h * HD_;
    const float* kbase = qbase + C_;
    const float* vbase = qbase + 2 * C_;

    // loader mapping: 128 threads, row = tid>>1 (0..63), col half = (tid&1)*32
    const int lrow = tid >> 1;
    const int lc0  = (tid & 1) * 32;

    // ---- load Q (scaled by 1/8, exact) and split ----
#pragma unroll
    for (int i = 0; i < 8; ++i) {
        float4 q = *(const float4*)(qbase + (size_t)(qb + lrow) * N3C + lc0 + 4 * i);
        q.x *= 0.125f; q.y *= 0.125f; q.z *= 0.125f; q.w *= 0.125f;
        uint32_t h0, l0, h1, l1;
        split2(q.x, q.y, h0, l0);
        split2(q.z, q.w, h1, l1);
        *(uint2*)&sA[lrow * AST + lc0 + 4 * i]       = make_uint2(h0, h1);
        *(uint2*)&sA[PLN + lrow * AST + lc0 + 4 * i] = make_uint2(l0, l1);
    }
    __syncthreads();

    // ---- extract Q A-frags (then smem region is reused for V^T) ----
    const int a_m = (lane & 7) + ((lane >> 3) & 1) * 8;
    const int a_k = (lane >> 4) * 8;
    const int b_r = (lane & 7) + ((lane >> 4) << 3);
    const int b_k = ((lane >> 3) & 1) * 8;

    uint32_t qfh[4][4], qfl[4][4];
#pragma unroll
    for (int ks = 0; ks < 4; ++ks) {
        const uint32_t ad = sAu + ((wm + a_m) * AST + ks * 16 + a_k) * 2;
        ldm4(qfh[ks][0], qfh[ks][1], qfh[ks][2], qfh[ks][3], ad);
        ldm4(qfl[ks][0], qfl[ks][1], qfl[ks][2], qfl[ks][3], ad + PLN * 2);
    }
    __syncthreads();   // all warps done with Q region before V overwrites it

    float m0r = -1e30f, m1r = -1e30f, l0r = 0.f, l1r = 0.f;
    float oacc[8][4];
#pragma unroll
    for (int nt = 0; nt < 8; ++nt)
#pragma unroll
        for (int q = 0; q < 4; ++q) oacc[nt][q] = 0.f;

    const int gr0 = qb + wm + (lane >> 2);   // global query row (and +8)
    const int njt = blockIdx.x + 1;

    for (int j = 0; j < njt; ++j) {
        const int jb = j * 64;

        // ---- stage K (natural) and V^T (transposed) with bf16 split ----
#pragma unroll
        for (int i = 0; i < 8; ++i) {
            const float4 kv = *(const float4*)(kbase + (size_t)(jb + lrow) * N3C + lc0 + 4 * i);
            uint32_t h0, l0, h1, l1;
            split2(kv.x, kv.y, h0, l0);
            split2(kv.z, kv.w, h1, l1);
            *(uint2*)&sB[lrow * AST + lc0 + 4 * i]       = make_uint2(h0, h1);
            *(uint2*)&sB[PLN + lrow * AST + lc0 + 4 * i] = make_uint2(l0, l1);

            const float4 vv = *(const float4*)(vbase + (size_t)(jb + lrow) * N3C + lc0 + 4 * i);
            const float ve[4] = {vv.x, vv.y, vv.z, vv.w};
#pragma unroll
            for (int e = 0; e < 4; ++e) {
                const __nv_bfloat16 hb = __float2bfloat16(ve[e]);
                const __nv_bfloat16 lb = __float2bfloat16(ve[e] - __bfloat162float(hb));
                sA[(lc0 + 4 * i + e) * AST + lrow]       = hb;   // V^T hi [hd][key]
                sA[PLN + (lc0 + 4 * i + e) * AST + lrow] = lb;   // V^T lo
            }
        }
        __syncthreads();

        // ---- S = Q K^T (3 cross MMAs), C-frags sacc[8][4] ----
        float sacc[8][4];
#pragma unroll
        for (int nt = 0; nt < 8; ++nt)
#pragma unroll
            for (int q = 0; q < 4; ++q) sacc[nt][q] = 0.f;

#pragma unroll
        for (int ks = 0; ks < 4; ++ks) {
#pragma unroll
            for (int p = 0; p < 4; ++p) {
                uint32_t bh0[2], bh1[2], bl0[2], bl1[2];
                const uint32_t bd = sBu + ((p * 16 + b_r) * AST + ks * 16 + b_k) * 2;
                ldm4(bh0[0], bh0[1], bh1[0], bh1[1], bd);
                ldm4(bl0[0], bl0[1], bl1[0], bl1[1], bd + PLN * 2);
                mma16816(sacc[2 * p],     qfh[ks], bh0);
                mma16816(sacc[2 * p],     qfh[ks], bl0);
                mma16816(sacc[2 * p],     qfl[ks], bh0);
                mma16816(sacc[2 * p + 1], qfh[ks], bh1);
                mma16816(sacc[2 * p + 1], qfh[ks], bl1);
                mma16816(sacc[2 * p + 1], qfl[ks], bh1);
            }
        }

        // ---- causal mask (diagonal tile only) ----
        if (j == njt - 1) {
#pragma unroll
            for (int nt = 0; nt < 8; ++nt) {
                const int col = jb + nt * 8 + (lane & 3) * 2;
                if (col     > gr0)     sacc[nt][0] = -1e30f;
                if (col + 1 > gr0)     sacc[nt][1] = -1e30f;
                if (col     > gr0 + 8) sacc[nt][2] = -1e30f;
                if (col + 1 > gr0 + 8) sacc[nt][3] = -1e30f;
            }
        }

        // ---- online softmax (rows r0 = lane>>2, r1 = r0+8; quad-shfl reduce) ----
        float mt0 = -1e30f, mt1 = -1e30f;
#pragma unroll
        for (int nt = 0; nt < 8; ++nt) {
            mt0 = fmaxf(mt0, fmaxf(sacc[nt][0], sacc[nt][1]));
            mt1 = fmaxf(mt1, fmaxf(sacc[nt][2], sacc[nt][3]));
        }
        mt0 = fmaxf(mt0, __shfl_xor_sync(0xffffffffu, mt0, 1));
        mt0 = fmaxf(mt0, __shfl_xor_sync(0xffffffffu, mt0, 2));
        mt1 = fmaxf(mt1, __shfl_xor_sync(0xffffffffu, mt1, 1));
        mt1 = fmaxf(mt1, __shfl_xor_sync(0xffffffffu, mt1, 2));
        const float mn0 = fmaxf(m0r, mt0), mn1 = fmaxf(m1r, mt1);
        const float cr0 = __expf(m0r - mn0), cr1 = __expf(m1r - mn1);
        m0r = mn0; m1r = mn1;

        float rs0 = 0.f, rs1 = 0.f;
#pragma unroll
        for (int nt = 0; nt < 8; ++nt) {
            sacc[nt][0] = __expf(sacc[nt][0] - mn0);
            sacc[nt][1] = __expf(sacc[nt][1] - mn0);
            sacc[nt][2] = __expf(sacc[nt][2] - mn1);
            sacc[nt][3] = __expf(sacc[nt][3] - mn1);
            rs0 += sacc[nt][0] + sacc[nt][1];
            rs1 += sacc[nt][2] + sacc[nt][3];
        }
        rs0 += __shfl_xor_sync(0xffffffffu, rs0, 1);
        rs0 += __shfl_xor_sync(0xffffffffu, rs0, 2);
        rs1 += __shfl_xor_sync(0xffffffffu, rs1, 1);
        rs1 += __shfl_xor_sync(0xffffffffu, rs1, 2);
        l0r = l0r * cr0 + rs0;
        l1r = l1r * cr1 + rs1;

#pragma unroll
        for (int nt = 0; nt < 8; ++nt) {
            oacc[nt][0] *= cr0; oacc[nt][1] *= cr0;
            oacc[nt][2] *= cr1; oacc[nt][3] *= cr1;
        }

        // ---- repack P: C-frag (sacc) -> A-frag bf16 hi/lo, in registers ----
        uint32_t pfh[4][4], pfl[4][4];
#pragma unroll
        for (int ks = 0; ks < 4; ++ks) {
            split2(sacc[2 * ks][0],     sacc[2 * ks][1],     pfh[ks][0], pfl[ks][0]);
            split2(sacc[2 * ks][2],     sacc[2 * ks][3],     pfh[ks][1], pfl[ks][1]);
            split2(sacc[2 * ks + 1][0], sacc[2 * ks + 1][1], pfh[ks][2], pfl[ks][2]);
            split2(sacc[2 * ks + 1][2], sacc[2 * ks + 1][3], pfh[ks][3], pfl[ks][3]);
        }

        // ---- O += P V  (V^T in sA region as B operand) ----
#pragma unroll
        for (int ks = 0; ks < 4; ++ks) {
#pragma unroll
            for (int p = 0; p < 4; ++p) {
                uint32_t bh0[2], bh1[2], bl0[2], bl1[2];
                const uint32_t bd = sAu + ((p * 16 + b_r) * AST + ks * 16 + b_k) * 2;
                ldm4(bh0[0], bh0[1], bh1[0], bh1[1], bd);
                ldm4(bl0[0], bl0[1], bl1[0], bl1[1], bd + PLN * 2);
                mma16816(oacc[2 * p],     pfh[ks], bh0);
                mma16816(oacc[2 * p],     pfh[ks], bl0);
                mma16816(oacc[2 * p],     pfl[ks], bh0);
                mma16816(oacc[2 * p + 1], pfh[ks], bh1);
                mma16816(oacc[2 * p + 1], pfh[ks], bl1);
                mma16816(oacc[2 * p + 1], pfl[ks], bh1);
            }
        }
        __syncthreads();   // done reading K/V^T before next tile overwrites
    }

    // ---- epilogue: normalize, split to bf16 hi/lo -> g_yh/g_yl ----
    const float inv0 = 1.0f / l0r, inv1 = 1.0f / l1r;
    const size_t orow0 = (size_t)(b * T_ + gr0) * C_ + h * HD_;
    const size_t orow1 = orow0 + 8 * C_;
#pragma unroll
    for (int nt = 0; nt < 8; ++nt) {
        const int col = nt * 8 + (lane & 3) * 2;
        uint32_t hp, lp;
        split2(oacc[nt][0] * inv0, oacc[nt][1] * inv0, hp, lp);
        *(uint32_t*)(g_yh + orow0 + col) = hp;
        *(uint32_t*)(g_yl + orow0 + col) = lp;
        split2(oacc[nt][2] * inv1, oacc[nt][3] * inv1, hp, lp);
        *(uint32_t*)(g_yh + orow1 + col) = hp;
        *(uint32_t*)(g_yl + orow1 + col) = lp;
    }
}

// ---------------------------------------------------------------------------
extern "C" void kernel_launch(void* const* d_in, const int* in_sizes, int n_in,
                              void* d_out, int out_size) {
    const float* x  = (const float*)d_in[0];  // [4,2048,1024]
    const float* Wa = (const float*)d_in[1];  // [1024,3072]
    const float* ba = (const float*)d_in[2];  // [3072]
    const float* Wp = (const float*)d_in[3];  // [1024,1024]
    const float* bp = (const float*)d_in[4];  // [1024]
    float* out = (float*)d_out;               // [4,2048,1024]
    (void)in_sizes; (void)n_in; (void)out_size;

    // Stage 0: splits (only harness pointers cross the launch boundary)
    k_split_x  <<<(M_ * C_) / 1024, 256>>>(x);
    k_split_wT <<<dim3(N3C / 32, C_ / 32), 256>>>(Wa, 0, N3C);
    k_split_wT <<<dim3(C_ / 32,  C_ / 32), 256>>>(Wp, 1, C_);

    // Stage 1: QKV GEMM (mma.sync bf16 split-2) -> g_qkv (bound device-side)
    k_gemm_mma <<<dim3(N3C / 128, M_ / 128), 256>>>(ba, nullptr, 0, N3C);

    // Stage 2: attention (mma.sync bf16 split-2)
    k_attn     <<<dim3(T_ / 64, B_ * NH_), 128>>>();

    // Stage 3: projection GEMM -> d_out
    k_gemm_mma <<<dim3(C_ / 128, M_ / 128), 256>>>(bp, out, 1, C_);
}